// round 3
// baseline (speedup 1.0000x reference)
#include <cuda_runtime.h>
#include <cuda_bf16.h>
#include <math.h>

// DynamicRouter: logits = x @ W^T + b + 0.1*noise ; top-2 ; sparse softmax.
// x[B=8,S=4096,D=768] f32, W[E=8,D=768] f32, b[8] f32, noise[B,S,8] f32.
// out: router_output [B,S,8] f32 (+ optionally top_k_indices [B,S,2] as f32).
//
// R3: packed f32x2 FFMA (sm_100a) + 2 tokens/warp + 4 CTAs/SM for latency hiding.

#define D_DIM        768
#define E_DIM        8
#define TOK_PER_WARP 2
#define WARPS        8
#define BLOCK        (WARPS * 32)
#define TOK_PER_BLK  (WARPS * TOK_PER_WARP)   // 16
#define D4           (D_DIM / 4)              // 192 (16B packets per token)
#define NOISE_STD    0.1f

// packed f32x2 FMA: acc = a*b + acc  (both halves independently)
#define FMA_F32X2(acc, a, b) \
    asm("fma.rn.f32x2 %0, %1, %2, %0;" : "+l"(acc) : "l"(a), "l"(b))

__global__ __launch_bounds__(BLOCK, 4)
void router_kernel(const float* __restrict__ x,
                   const float* __restrict__ W,
                   const float* __restrict__ b,
                   const float* __restrict__ noise,
                   float* __restrict__ out,
                   int nTokens, int writeIdx)
{
    __shared__ float sW[E_DIM * D_DIM];   // 24 KB

    const int tid  = threadIdx.x;
    const int lane = tid & 31;
    const int wid  = tid >> 5;

    // Stage W into shared (coalesced float4 copy of contiguous 24 KB)
    {
        const float4* Wg = reinterpret_cast<const float4*>(W);
        float4*       Ws = reinterpret_cast<float4*>(sW);
        #pragma unroll
        for (int i = 0; i < (E_DIM * D4) / BLOCK; i++)
            Ws[i * BLOCK + tid] = Wg[i * BLOCK + tid];
    }
    __syncthreads();

    const int tokBase = blockIdx.x * TOK_PER_BLK + wid * TOK_PER_WARP;
    if (tokBase >= nTokens) return;

    // 16B packets viewed as 2x packed-f32x2: .x = {v0,v1}, .y = {v2,v3}
    const ulonglong2* xp  = reinterpret_cast<const ulonglong2*>(x) + (size_t)tokBase * D4;
    const ulonglong2* sW2 = reinterpret_cast<const ulonglong2*>(sW);

    // packed accumulators: pacc[t][e] = f32x2 {even-pair partial, odd-pair partial}
    unsigned long long pacc[TOK_PER_WARP][E_DIM];
    #pragma unroll
    for (int t = 0; t < TOK_PER_WARP; t++)
        #pragma unroll
        for (int e = 0; e < E_DIM; e++) pacc[t][e] = 0ull;

    // Main loop: 6 chunks of 32 packet positions; lane owns position i*32+lane.
    #pragma unroll 2
    for (int i = 0; i < D4 / 32; i++) {
        const int p = i * 32 + lane;
        ulonglong2 xv[TOK_PER_WARP];
        #pragma unroll
        for (int t = 0; t < TOK_PER_WARP; t++)
            xv[t] = xp[(size_t)t * D4 + p];            // coalesced 512B/token/warp
        #pragma unroll
        for (int e = 0; e < E_DIM; e++) {
            const ulonglong2 wv = sW2[e * D4 + p];     // LDS.128, reused x2 tokens
            #pragma unroll
            for (int t = 0; t < TOK_PER_WARP; t++) {
                FMA_F32X2(pacc[t][e], xv[t].x, wv.x);
                FMA_F32X2(pacc[t][e], xv[t].y, wv.y);
            }
        }
    }

    // Unpack into 32 scalar partials, value index v = half*16 + t*8 + e.
    float acc[32];
    #pragma unroll
    for (int t = 0; t < TOK_PER_WARP; t++)
        #pragma unroll
        for (int e = 0; e < E_DIM; e++) {
            unsigned int lo, hi;
            asm("mov.b64 {%0,%1}, %2;" : "=r"(lo), "=r"(hi) : "l"(pacc[t][e]));
            acc[      t * E_DIM + e] = __uint_as_float(lo);
            acc[16 +  t * E_DIM + e] = __uint_as_float(hi);
        }

    // Log-halving butterfly: after 5 steps lane l holds the full 32-lane sum
    // of value index v == l.
    #pragma unroll
    for (int m = 16; m >= 1; m >>= 1) {
        const bool upper = (lane & m) != 0;
        #pragma unroll
        for (int i = 0; i < m; i++) {
            const float lo = acc[i], hi = acc[i + m];
            const float send = upper ? lo : hi;
            const float recv = __shfl_xor_sync(0xFFFFFFFFu, send, m);
            acc[i] = upper ? (hi + recv) : (lo + recv);
        }
    }
    // Fold the two halves (v and v+16): lane l now holds logit-sum for k = l&15.
    float s = acc[0];
    s += __shfl_xor_sync(0xFFFFFFFFu, s, 16);

    const int k = lane & 15;        // k = t*8 + e
    const int t = k >> 3;           // token within warp (0..1)
    const int e = k & 7;            // expert
    const long tok = (long)tokBase + t;

    const float logit = s + __ldg(b + e)
                      + NOISE_STD * __ldg(noise + (size_t)tokBase * E_DIM + k);

    // top-1 over the 8-lane expert group (ties -> lower index, jax top_k order)
    float v1 = logit; int i1 = e;
    #pragma unroll
    for (int off = 1; off < 8; off <<= 1) {
        const float ov = __shfl_xor_sync(0xFFFFFFFFu, v1, off);
        const int   oi = __shfl_xor_sync(0xFFFFFFFFu, i1, off);
        if (ov > v1 || (ov == v1 && oi < i1)) { v1 = ov; i1 = oi; }
    }
    // top-2: exclude winner, reduce again
    float v2 = (e == i1) ? -INFINITY : logit; int i2 = e;
    #pragma unroll
    for (int off = 1; off < 8; off <<= 1) {
        const float ov = __shfl_xor_sync(0xFFFFFFFFu, v2, off);
        const int   oi = __shfl_xor_sync(0xFFFFFFFFu, i2, off);
        if (ov > v2 || (ov == v2 && oi < i2)) { v2 = ov; i2 = oi; }
    }

    // 2-element softmax: p1 = 1/(1+exp(v2-v1)), p2 = exp(v2-v1)*p1  (arg <= 0)
    const float ed  = __expf(v2 - v1);
    const float inv = 1.0f / (1.0f + ed);
    const float p   = (e == i1) ? inv : ((e == i2) ? ed * inv : 0.0f);

    if (lane < 16) {
        out[(size_t)tokBase * E_DIM + k] = p;   // 64B contiguous per warp
        if (writeIdx && e == 0) {
            float* idxOut = out + (size_t)nTokens * E_DIM;
            idxOut[tok * 2 + 0] = (float)i1;
            idxOut[tok * 2 + 1] = (float)i2;
        }
    }
}

extern "C" void kernel_launch(void* const* d_in, const int* in_sizes, int n_in,
                              void* d_out, int out_size)
{
    const float* x     = (const float*)d_in[0];
    const float* W     = (const float*)d_in[1];
    const float* b     = (const float*)d_in[2];
    const float* noise = (const float*)d_in[3];
    float* out = (float*)d_out;

    const int nTokens = in_sizes[3] / E_DIM;          // B*S from noise elem count
    const int writeIdx = (out_size >= nTokens * E_DIM + nTokens * 2) ? 1 : 0;

    const int grid = (nTokens + TOK_PER_BLK - 1) / TOK_PER_BLK;
    router_kernel<<<grid, BLOCK>>>(x, W, b, noise, out, nTokens, writeIdx);
}

// round 4
// speedup vs baseline: 1.2962x; 1.2962x over previous
#include <cuda_runtime.h>
#include <cuda_bf16.h>
#include <math.h>

// DynamicRouter: logits = x @ W^T + b + 0.1*noise ; top-2 ; sparse softmax.
// x[B=8,S=4096,D=768] f32, W[E=8,D=768] f32, b[8] f32, noise[B,S,8] f32.
// out: router_output [B,S,8] f32 (+ optionally top_k_indices [B,S,2] as f32).
//
// R4: back to TOK=4 (best L1/LDS amortization) + 1-chunk-deep register
// prefetch so every warp keeps 4 LDG.128 in flight through the compute tail.

#define D_DIM        768
#define E_DIM        8
#define TOK_PER_WARP 4
#define WARPS        8
#define BLOCK        (WARPS * 32)
#define TOK_PER_BLK  (WARPS * TOK_PER_WARP)   // 32
#define D4           (D_DIM / 4)              // 192
#define NCHUNK       (D4 / 32)                // 6
#define NOISE_STD    0.1f

__global__ __launch_bounds__(BLOCK, 3)
void router_kernel(const float* __restrict__ x,
                   const float* __restrict__ W,
                   const float* __restrict__ b,
                   const float* __restrict__ noise,
                   float* __restrict__ out,
                   int nTokens, int writeIdx)
{
    __shared__ float sW[E_DIM * D_DIM];   // 24 KB

    const int tid  = threadIdx.x;
    const int lane = tid & 31;
    const int wid  = tid >> 5;

    // Stage W into shared (coalesced float4 copy of contiguous 24 KB)
    {
        const float4* Wg = reinterpret_cast<const float4*>(W);
        float4*       Ws = reinterpret_cast<float4*>(sW);
        #pragma unroll
        for (int i = 0; i < (E_DIM * D4) / BLOCK; i++)
            Ws[i * BLOCK + tid] = Wg[i * BLOCK + tid];
    }
    __syncthreads();

    const int tokBase = blockIdx.x * TOK_PER_BLK + wid * TOK_PER_WARP;
    if (tokBase >= nTokens) return;

    const float4* x4  = reinterpret_cast<const float4*>(x) + (size_t)tokBase * D4;
    const float4* sW4 = reinterpret_cast<const float4*>(sW);

    // acc[t*8+e] : token t (0..3) x expert e (0..7)
    float acc[TOK_PER_WARP * E_DIM];
    #pragma unroll
    for (int v = 0; v < TOK_PER_WARP * E_DIM; v++) acc[v] = 0.0f;

    // ---- software-pipelined main loop: prefetch chunk i+1 while computing i ----
    float4 cur[TOK_PER_WARP], nxt[TOK_PER_WARP];
    #pragma unroll
    for (int t = 0; t < TOK_PER_WARP; t++)
        cur[t] = x4[(size_t)t * D4 + lane];            // chunk 0

    #pragma unroll 1
    for (int i = 0; i < NCHUNK; i++) {
        // issue next chunk's loads FIRST: 4 LDG.128 in flight during compute
        if (i + 1 < NCHUNK) {
            const int pn = (i + 1) * 32 + lane;
            #pragma unroll
            for (int t = 0; t < TOK_PER_WARP; t++)
                nxt[t] = x4[(size_t)t * D4 + pn];       // coalesced 512B/token
        }
        const int p = i * 32 + lane;
        #pragma unroll
        for (int e = 0; e < E_DIM; e++) {
            const float4 wv = sW4[e * D4 + p];          // LDS.128, reused x4 tokens
            #pragma unroll
            for (int t = 0; t < TOK_PER_WARP; t++) {
                acc[t * E_DIM + e] += cur[t].x * wv.x + cur[t].y * wv.y
                                    + cur[t].z * wv.z + cur[t].w * wv.w;
            }
        }
        #pragma unroll
        for (int t = 0; t < TOK_PER_WARP; t++) cur[t] = nxt[t];   // rotate
    }

    // Log-halving butterfly: after 5 steps lane l holds the complete 32-lane
    // sum for value index v == l  (v = t*8 + e).
    #pragma unroll
    for (int m = 16; m >= 1; m >>= 1) {
        const bool upper = (lane & m) != 0;
        #pragma unroll
        for (int i = 0; i < m; i++) {
            const float lo = acc[i], hi = acc[i + m];
            const float send = upper ? lo : hi;
            const float recv = __shfl_xor_sync(0xFFFFFFFFu, send, m);
            acc[i] = upper ? (hi + recv) : (lo + recv);
        }
    }
    const float sum = acc[0];

    // lane l -> token t = l>>3, expert e = l&7
    const int t = lane >> 3;
    const int e = lane & 7;
    const long tok = (long)tokBase + t;

    // noise: lane l reads noise[tokBase*8 + l] -> contiguous 128B/warp
    const float logit = sum + __ldg(b + e)
                      + NOISE_STD * __ldg(noise + (size_t)tokBase * E_DIM + lane);

    // top-1 over the 8-lane expert group (ties -> lower index, jax top_k order)
    float v1 = logit; int i1 = e;
    #pragma unroll
    for (int off = 1; off < 8; off <<= 1) {
        const float ov = __shfl_xor_sync(0xFFFFFFFFu, v1, off);
        const int   oi = __shfl_xor_sync(0xFFFFFFFFu, i1, off);
        if (ov > v1 || (ov == v1 && oi < i1)) { v1 = ov; i1 = oi; }
    }
    // top-2: exclude winner, reduce again
    float v2 = (e == i1) ? -INFINITY : logit; int i2 = e;
    #pragma unroll
    for (int off = 1; off < 8; off <<= 1) {
        const float ov = __shfl_xor_sync(0xFFFFFFFFu, v2, off);
        const int   oi = __shfl_xor_sync(0xFFFFFFFFu, i2, off);
        if (ov > v2 || (ov == v2 && oi < i2)) { v2 = ov; i2 = oi; }
    }

    // 2-element softmax: p1 = 1/(1+exp(v2-v1)), p2 = exp(v2-v1)*p1  (arg <= 0)
    const float ed  = __expf(v2 - v1);
    const float inv = 1.0f / (1.0f + ed);
    const float p   = (e == i1) ? inv : ((e == i2) ? ed * inv : 0.0f);

    // coalesced 128B write per warp
    out[(size_t)tokBase * E_DIM + lane] = p;

    if (writeIdx && e == 0) {
        float* idxOut = out + (size_t)nTokens * E_DIM;
        idxOut[tok * 2 + 0] = (float)i1;
        idxOut[tok * 2 + 1] = (float)i2;
    }
}

extern "C" void kernel_launch(void* const* d_in, const int* in_sizes, int n_in,
                              void* d_out, int out_size)
{
    const float* x     = (const float*)d_in[0];
    const float* W     = (const float*)d_in[1];
    const float* b     = (const float*)d_in[2];
    const float* noise = (const float*)d_in[3];
    float* out = (float*)d_out;

    const int nTokens = in_sizes[3] / E_DIM;          // B*S from noise elem count
    const int writeIdx = (out_size >= nTokens * E_DIM + nTokens * 2) ? 1 : 0;

    const int grid = (nTokens + TOK_PER_BLK - 1) / TOK_PER_BLK;
    router_kernel<<<grid, BLOCK>>>(x, W, b, noise, out, nTokens, writeIdx);
}

// round 7
// speedup vs baseline: 1.3333x; 1.0286x over previous
#include <cuda_runtime.h>
#include <cuda_bf16.h>
#include <math.h>

// DynamicRouter: logits = x @ W^T + b + 0.1*noise ; top-2 ; sparse softmax.
// x[B=8,S=4096,D=768] f32, W[E=8,D=768] f32, b[8] f32, noise[B,S,8] f32.
//
// R7: cp.async.cg staging of x through a 3-stage per-warp smem ring.
// Fire-and-forget copies keep 3 committed groups (6KB) in flight per warp at
// all times -> ~100KB outstanding bytes per SM, saturating HBM. Each lane
// reads back only bytes it wrote, so cp.async.wait_group is the ONLY sync.

#define D_DIM        768
#define E_DIM        8
#define TOK_PER_WARP 4
#define WARPS        8
#define BLOCK        (WARPS * 32)
#define TOK_PER_BLK  (WARPS * TOK_PER_WARP)   // 32
#define D4           (D_DIM / 4)              // 192
#define NCHUNK       (D4 / 32)                // 6
#define NSTAGE       3
#define SW_F4        (E_DIM * D4)             // 1536 float4 = 24 KB
#define SX_WARP_F4   (NSTAGE * TOK_PER_WARP * 32)   // 384 float4 = 6 KB/warp
#define SMEM_BYTES   ((SW_F4 + WARPS * SX_WARP_F4) * 16)  // 73728
#define NOISE_STD    0.1f

#define CP_ASYNC16(dst32, src) \
    asm volatile("cp.async.cg.shared.global [%0], [%1], 16;" \
                 :: "r"(dst32), "l"(src) : "memory")
#define CP_COMMIT() asm volatile("cp.async.commit_group;" ::: "memory")
#define CP_WAIT(n)  asm volatile("cp.async.wait_group %0;" :: "n"(n) : "memory")

__global__ __launch_bounds__(BLOCK, 3)
void router_kernel(const float* __restrict__ x,
                   const float* __restrict__ W,
                   const float* __restrict__ b,
                   const float* __restrict__ noise,
                   float* __restrict__ out,
                   int nTokens, int writeIdx)
{
    extern __shared__ float4 smem[];
    float4* sW4 = smem;                 // [E_DIM * D4]
    float4* sX  = smem + SW_F4;         // [WARPS][NSTAGE][TOK*32]

    const int tid  = threadIdx.x;
    const int lane = tid & 31;
    const int wid  = tid >> 5;

    // Stage W into shared once (coalesced float4 copy of contiguous 24 KB)
    {
        const float4* Wg = reinterpret_cast<const float4*>(W);
        #pragma unroll
        for (int i = 0; i < SW_F4 / BLOCK; i++)
            sW4[i * BLOCK + tid] = Wg[i * BLOCK + tid];
    }
    __syncthreads();

    const int tokBase = blockIdx.x * TOK_PER_BLK + wid * TOK_PER_WARP;
    if (tokBase >= nTokens) return;

    const float4* x4 = reinterpret_cast<const float4*>(x) + (size_t)tokBase * D4;

    // per-warp ring base (smem address space)
    float4* myX = sX + wid * SX_WARP_F4;
    const unsigned myX32 = (unsigned)__cvta_generic_to_shared(myX);

    float acc[TOK_PER_WARP * E_DIM];
    #pragma unroll
    for (int v = 0; v < TOK_PER_WARP * E_DIM; v++) acc[v] = 0.0f;

    // issue chunk c into ring stage s: 4x cp.async(16B) per lane, one group.
    // (lambda in device code is implicitly device; no annotation needed)
    auto issue = [&](int c, int s) {
        #pragma unroll
        for (int t = 0; t < TOK_PER_WARP; t++)
            CP_ASYNC16(myX32 + (unsigned)(((s * TOK_PER_WARP + t) * 32 + lane) * 16),
                       x4 + (size_t)t * D4 + c * 32 + lane);
        CP_COMMIT();
    };

    // compute chunk c from ring stage s (each lane reads only its own writes)
    auto compute = [&](int c, int s) {
        float4 xv[TOK_PER_WARP];
        #pragma unroll
        for (int t = 0; t < TOK_PER_WARP; t++)
            xv[t] = myX[(s * TOK_PER_WARP + t) * 32 + lane];
        const int p = c * 32 + lane;
        #pragma unroll
        for (int e = 0; e < E_DIM; e++) {
            const float4 wv = sW4[e * D4 + p];       // LDS.128, reused x4 tokens
            #pragma unroll
            for (int t = 0; t < TOK_PER_WARP; t++)
                acc[t * E_DIM + e] += xv[t].x * wv.x + xv[t].y * wv.y
                                    + xv[t].z * wv.z + xv[t].w * wv.w;
        }
    };

    // fully unrolled 3-deep pipeline over 6 chunks
    issue(0, 0); issue(1, 1); issue(2, 2);           // pending: 3
    CP_WAIT(2); compute(0, 0); issue(3, 0);          // chunk0 ready; pending 3
    CP_WAIT(2); compute(1, 1); issue(4, 1);
    CP_WAIT(2); compute(2, 2); issue(5, 2);
    CP_WAIT(2); compute(3, 0);                       // pending 2
    CP_WAIT(1); compute(4, 1);
    CP_WAIT(0); compute(5, 2);

    // Log-halving butterfly: after 5 steps lane l holds the complete 32-lane
    // sum for value index v == l  (v = t*8 + e).
    #pragma unroll
    for (int m = 16; m >= 1; m >>= 1) {
        const bool upper = (lane & m) != 0;
        #pragma unroll
        for (int i = 0; i < m; i++) {
            const float lo = acc[i], hi = acc[i + m];
            const float send = upper ? lo : hi;
            const float recv = __shfl_xor_sync(0xFFFFFFFFu, send, m);
            acc[i] = upper ? (hi + recv) : (lo + recv);
        }
    }
    const float sum = acc[0];

    const int t = lane >> 3;            // token within warp
    const int e = lane & 7;             // expert
    const long tok = (long)tokBase + t;

    const float logit = sum + __ldg(b + e)
                      + NOISE_STD * __ldg(noise + (size_t)tokBase * E_DIM + lane);

    // top-1 over the 8-lane expert group (ties -> lower index, jax top_k order)
    float v1 = logit; int i1 = e;
    #pragma unroll
    for (int off = 1; off < 8; off <<= 1) {
        const float ov = __shfl_xor_sync(0xFFFFFFFFu, v1, off);
        const int   oi = __shfl_xor_sync(0xFFFFFFFFu, i1, off);
        if (ov > v1 || (ov == v1 && oi < i1)) { v1 = ov; i1 = oi; }
    }
    // top-2: exclude winner, reduce again
    float v2 = (e == i1) ? -INFINITY : logit; int i2 = e;
    #pragma unroll
    for (int off = 1; off < 8; off <<= 1) {
        const float ov = __shfl_xor_sync(0xFFFFFFFFu, v2, off);
        const int   oi = __shfl_xor_sync(0xFFFFFFFFu, i2, off);
        if (ov > v2 || (ov == v2 && oi < i2)) { v2 = ov; i2 = oi; }
    }

    // 2-element softmax: p1 = 1/(1+exp(v2-v1)), p2 = exp(v2-v1)*p1  (arg <= 0)
    const float ed  = __expf(v2 - v1);
    const float inv = 1.0f / (1.0f + ed);
    const float p   = (e == i1) ? inv : ((e == i2) ? ed * inv : 0.0f);

    out[(size_t)tokBase * E_DIM + lane] = p;   // coalesced 128B per warp

    if (writeIdx && e == 0) {
        float* idxOut = out + (size_t)nTokens * E_DIM;
        idxOut[tok * 2 + 0] = (float)i1;
        idxOut[tok * 2 + 1] = (float)i2;
    }
}

extern "C" void kernel_launch(void* const* d_in, const int* in_sizes, int n_in,
                              void* d_out, int out_size)
{
    const float* x     = (const float*)d_in[0];
    const float* W     = (const float*)d_in[1];
    const float* b     = (const float*)d_in[2];
    const float* noise = (const float*)d_in[3];
    float* out = (float*)d_out;

    const int nTokens = in_sizes[3] / E_DIM;          // B*S from noise elem count
    const int writeIdx = (out_size >= nTokens * E_DIM + nTokens * 2) ? 1 : 0;

    // >48KB dynamic smem needs explicit opt-in. Unconditional (no static
    // guards per harness rules): idempotent, not stream-ordered, capture-safe.
    cudaFuncSetAttribute(router_kernel,
                         cudaFuncAttributeMaxDynamicSharedMemorySize,
                         SMEM_BYTES);

    const int grid = (nTokens + TOK_PER_BLK - 1) / TOK_PER_BLK;
    router_kernel<<<grid, BLOCK, SMEM_BYTES>>>(x, W, b, noise, out, nTokens, writeIdx);
}